// round 13
// baseline (speedup 1.0000x reference)
#include <cuda_runtime.h>

// QuantumLinear closed form — occupancy-optimized (single resident wave).
//
// Closed form (X-basis Walsh collapse), a_q = x_q + w0_q, b_q = w1_q:
//   z0 = 1/2[cos(a1+a3)cos(a0+b3)cos(b1+b2) + cos(a1-a3)cos(a0-b3)cos(b1-b2)]
//   z1 = 1/2 cos(a3)[cos(a0+a2)cos(b0+b1) + cos(a0-a2)cos(b0-b1)]
//   z2 = 1/2 cos(b0)[cos(a1+a3)cos(b1+b2) + cos(a1-a3)cos(b1-b2)]
//   z3 = 1/2[cos(b2+b3)cos(a2+b0)cos(a0+b1) + cos(b2-b3)cos(a2-b0)cos(a0-b1)]
//
// R9 evidence: kernel is latency-bound (nothing >40% utilized), and the
// 1024-block grid at 6 blocks/SM left a ~130-block second wave running at
// 12% occupancy. Fix: cap regs at 32 (__launch_bounds__(256, 8)) so all
// 1024 blocks are resident in ONE wave (152 SMs x 8 blocks = 1216 slots),
// occupancy ~84%. Loads are just-in-time (cross-warp parallelism covers
// latency at 54 warps/SM); default cache ops keep x L2-resident across
// graph replays (measured: HBM traffic is already ~half of footprint).

#define QL_BDIM 256
#define SPT 4            // sims per thread

__global__ __launch_bounds__(QL_BDIM, 8)   // forces <=32 regs -> 8 blocks/SM
void ql_closed_kernel(const float4* __restrict__ x4,
                      const float4* __restrict__ w4,
                      float4* __restrict__ out4,
                      int nthreads)          // = total_sims / SPT, multiple of 256
{
    int t = blockIdx.x * QL_BDIM + threadIdx.x;
    if (t >= nthreads) return;
    int c = t & 255;                          // circuit index, same for all SPT sims

    float4 w0 = w4[2 * c];
    float4 w1 = w4[2 * c + 1];
    float b0 = w1.x, b1 = w1.y, b2 = w1.z, b3 = w1.w;

    // weight-only constants (1/2 folded in) — computed once per thread
    float h12p = 0.5f * __cosf(b1 + b2);
    float h12m = 0.5f * __cosf(b1 - b2);
    float h01p = 0.5f * __cosf(b0 + b1);
    float h01m = 0.5f * __cosf(b0 - b1);
    float cb0  = __cosf(b0);
    float g12p = cb0 * h12p;                  // for z2
    float g12m = cb0 * h12m;
    float h23p = 0.5f * __cosf(b2 + b3);
    float h23m = 0.5f * __cosf(b2 - b3);

#pragma unroll
    for (int s = 0; s < SPT; s++) {
        int idx = t + s * nthreads;           // coalesced across the warp
        float4 xv = x4[idx];                  // JIT load; occupancy hides latency
        float a0 = xv.x + w0.x;
        float a1 = xv.y + w0.y;
        float a2 = xv.z + w0.z;
        float a3 = xv.w + w0.w;

        float ca13p = __cosf(a1 + a3);
        float ca13m = __cosf(a1 - a3);

        float c0p = __cosf(a0 + b3);
        float c0m = __cosf(a0 - b3);
        float z0 = fmaf(ca13m * c0m, h12m, (ca13p * c0p) * h12p);

        float ca3  = __cosf(a3);
        float c02p = __cosf(a0 + a2);
        float c02m = __cosf(a0 - a2);
        float z1 = ca3 * fmaf(c02m, h01m, c02p * h01p);

        float z2 = fmaf(ca13m, g12m, ca13p * g12p);

        float c20p = __cosf(a2 + b0);
        float c20m = __cosf(a2 - b0);
        float c01p = __cosf(a0 + b1);
        float c01m = __cosf(a0 - b1);
        float z3 = fmaf(h23m * c20m, c01m, (h23p * c20p) * c01p);

        out4[idx] = make_float4(z0, z1, z2, z3);
    }
}

extern "C" void kernel_launch(void* const* d_in, const int* in_sizes, int n_in,
                              void* d_out, int out_size)
{
    const float4* x4 = (const float4*)d_in[0];   // x: (4096, 1024) f32
    const float4* w4 = (const float4*)d_in[1];   // weights: (256, 2, 4) f32
    float4* o4 = (float4*)d_out;                 // out: (4096, 1024) f32

    int total = in_sizes[0] / 4;                 // 1,048,576 sims
    int nthreads = total / SPT;                  // 262,144 (multiple of 256)
    int grid = (nthreads + QL_BDIM - 1) / QL_BDIM;   // 1024 blocks -> 1 wave @ 8/SM
    ql_closed_kernel<<<grid, QL_BDIM>>>(x4, w4, o4, nthreads);
}